// round 2
// baseline (speedup 1.0000x reference)
#include <cuda_runtime.h>
#include <cuda_bf16.h>

// ---------------------------------------------------------------------------
// Classifier: out[e] = MLP(concat(x_drug[i_e], x_disease[j_e]))
// Factorization: layer-1 GEMM is precomputed per-node:
//   h_drug    = x_drug    @ W1[0:100]   + b1     (10000 x 128)
//   h_disease = x_disease @ W1[100:200]          (10000 x 128)
// per edge: h = leaky(h_drug[i] + h_disease[j]); then 128->32->16->1.
// ---------------------------------------------------------------------------

#define MAX_NODES 16384
__device__ float g_hd[MAX_NODES * 128];
__device__ float g_he[MAX_NODES * 128];
__device__ int   g_idx64;   // 1 if edge index buffer is int64, 0 if int32

__device__ __forceinline__ float lrelu(float v) {
    return v >= 0.0f ? v : 0.01f * v;
}

// packed f32x2 helpers (sm_100+/sm_103a; ptxas never auto-generates these)
__device__ __forceinline__ unsigned long long pk2(float a, float b) {
    unsigned long long r;
    asm("mov.b64 %0, {%1, %2};" : "=l"(r) : "f"(a), "f"(b));
    return r;
}
__device__ __forceinline__ void up2(unsigned long long v, float& a, float& b) {
    asm("mov.b64 {%0, %1}, %2;" : "=f"(a), "=f"(b) : "l"(v));
}
__device__ __forceinline__ unsigned long long fma2(unsigned long long a,
                                                   unsigned long long b,
                                                   unsigned long long c) {
    unsigned long long d;
    asm("fma.rn.f32x2 %0, %1, %2, %3;" : "=l"(d) : "l"(a), "l"(b), "l"(c));
    return d;
}

// ---------------------------------------------------------------------------
// Kernel 0: detect edge-index dtype. JAX without x64 silently emits int32
// even though the reference declares int64. Real int64 indices are <10000,
// so any "int64" view value outside [0, 1e6) means the buffer is int32.
// ---------------------------------------------------------------------------
__global__ void detect_idx_dtype(const long long* __restrict__ ell) {
    int ok64 = 1;
#pragma unroll
    for (int t = 0; t < 8; t++) {
        long long v = ell[t];
        if (v < 0 || v >= 1000000) ok64 = 0;
    }
    g_idx64 = ok64;
}

__device__ __forceinline__ long long load_idx(const void* ell, long long pos,
                                              int is64) {
    if (is64) return ((const long long*)ell)[pos];
    return (long long)((const int*)ell)[pos];
}

// ---------------------------------------------------------------------------
// Kernel 1: per-node layer-1 precompute.
// grid = n_drug + n_dis blocks, 128 threads. Thread m computes output dim m.
// ---------------------------------------------------------------------------
__global__ void node_precompute(const float* __restrict__ xd,
                                const float* __restrict__ xs,
                                const float* __restrict__ W1,
                                const float* __restrict__ b1,
                                int n_drug, int n_dis) {
    int nid = blockIdx.x;
    bool is_drug = nid < n_drug;
    const float* x = is_drug ? (xd + (long)nid * 100)
                             : (xs + (long)(nid - n_drug) * 100);
    const float* w = W1 + (is_drug ? 0 : 100 * 128);
    float* out = is_drug ? (g_hd + (long)nid * 128)
                         : (g_he + (long)(nid - n_drug) * 128);

    __shared__ float xsh[100];
    int t = threadIdx.x;
    if (t < 100) xsh[t] = x[t];
    __syncthreads();

    float acc = is_drug ? b1[t] : 0.0f;
#pragma unroll 4
    for (int k = 0; k < 100; k++)
        acc = fmaf(xsh[k], __ldg(&w[k * 128 + t]), acc);
    out[t] = acc;
}

// ---------------------------------------------------------------------------
// Kernel 2: per-edge MLP.
// Block = 256 threads, tile = 128 edges.
// Phase 1: gather h_drug[i]+h_disease[j], leaky, stage in smem (stride 132).
// Phase 2: 128x32 GEMM (K=128) with f32x2 packed FMAs, 4e x 4m register tile.
// Phase 3: layers 3+4 per edge (thread-per-edge), f32x2.
// ---------------------------------------------------------------------------
#define EPB        128
#define NTHR       256
#define HS_STRIDE  132
#define O2_STRIDE  36

// smem layout (floats)
#define OFF_HS   0
#define OFF_WS2  (OFF_HS  + EPB * HS_STRIDE)       // 16896
#define OFF_O2   (OFF_WS2 + 128 * 32)              // 20992
#define OFF_W3   (OFF_O2  + EPB * O2_STRIDE)       // 25600
#define OFF_W4   (OFF_W3  + 32 * 16)               // 26112
#define OFF_B2   (OFF_W4  + 16)                    // 26128
#define OFF_B3   (OFF_B2  + 32)                    // 26160
#define SMEM_FLOATS (OFF_B3 + 16)                  // 26176
#define SMEM_BYTES (SMEM_FLOATS * 4)               // 104704

__global__ void __launch_bounds__(NTHR, 1)
edge_mlp_kernel(const void* __restrict__ ell,
                const float* __restrict__ W2, const float* __restrict__ b2,
                const float* __restrict__ W3, const float* __restrict__ b3,
                const float* __restrict__ W4, const float* __restrict__ b4,
                float* __restrict__ out, int E) {
    extern __shared__ float sm[];
    float* hs  = sm + OFF_HS;
    float* ws2 = sm + OFF_WS2;
    float* o2  = sm + OFF_O2;
    float* w3s = sm + OFF_W3;
    float* w4s = sm + OFF_W4;
    float* b2s = sm + OFF_B2;
    float* b3s = sm + OFF_B3;

    const int tid  = threadIdx.x;
    const int warp = tid >> 5;
    const int lane = tid & 31;
    const int is64 = g_idx64;

    // ---- stage weights ----
    for (int i = tid; i < 128 * 32; i += NTHR) ws2[i] = W2[i];
    for (int i = tid; i < 32 * 16;  i += NTHR) w3s[i] = W3[i];
    if (tid < 16) w4s[tid] = W4[tid];
    if (tid < 32) b2s[tid] = b2[tid];
    if (tid < 16) b3s[tid] = b3[tid];

    // ---- phase 1: gather + combine ----
    // warp w handles 16 edges; lanes 0..15 hold i-indices, 16..31 hold j.
    {
        int ebase = blockIdx.x * EPB + warp * 16;
        int e = ebase + (lane & 15);
        int ec = e < E ? e : (E - 1);
        long long pos = (lane < 16) ? (long long)ec : (long long)E + ec;
        long long v = load_idx(ell, pos, is64);

#pragma unroll
        for (int t = 0; t < 16; t++) {
            long long i = __shfl_sync(0xffffffffu, v, t);
            long long j = __shfl_sync(0xffffffffu, v, 16 + t);
            int er = warp * 16 + t;  // local row in [0,128)
            const float4 a = *(const float4*)&g_hd[i * 128 + lane * 4];
            const float4 b = *(const float4*)&g_he[j * 128 + lane * 4];
            float4 s;
            s.x = lrelu(a.x + b.x);
            s.y = lrelu(a.y + b.y);
            s.z = lrelu(a.z + b.z);
            s.w = lrelu(a.w + b.w);
            *(float4*)&hs[er * HS_STRIDE + lane * 4] = s;
        }
    }
    __syncthreads();

    // ---- phase 2: [128e x 32m] = hs[128e x 128k] @ W2[128k x 32m] ----
    // thread tile: 4 edges x 4 m. te = tid>>3 (0..31), tm = tid&7 (0..7).
    {
        const int te = tid >> 3;
        const int tm = tid & 7;
        const float* h0 = hs + (4 * te + 0) * HS_STRIDE;
        const float* h1 = hs + (4 * te + 1) * HS_STRIDE;
        const float* h2 = hs + (4 * te + 2) * HS_STRIDE;
        const float* h3 = hs + (4 * te + 3) * HS_STRIDE;

        unsigned long long acc[4][2];
#pragma unroll
        for (int r = 0; r < 4; r++) { acc[r][0] = 0ull; acc[r][1] = 0ull; }

#pragma unroll 4
        for (int k = 0; k < 128; k += 4) {
            ulonglong2 w0  = *(const ulonglong2*)&ws2[(k + 0) * 32 + 4 * tm];
            ulonglong2 w1  = *(const ulonglong2*)&ws2[(k + 1) * 32 + 4 * tm];
            ulonglong2 w2  = *(const ulonglong2*)&ws2[(k + 2) * 32 + 4 * tm];
            ulonglong2 w3v = *(const ulonglong2*)&ws2[(k + 3) * 32 + 4 * tm];

            float4 hv;
            unsigned long long hb;
#pragma unroll
            for (int r = 0; r < 4; r++) {
                const float* hp = (r == 0) ? h0 : (r == 1) ? h1 : (r == 2) ? h2 : h3;
                hv = *(const float4*)&hp[k];
                hb = pk2(hv.x, hv.x);
                acc[r][0] = fma2(hb, w0.x, acc[r][0]);
                acc[r][1] = fma2(hb, w0.y, acc[r][1]);
                hb = pk2(hv.y, hv.y);
                acc[r][0] = fma2(hb, w1.x, acc[r][0]);
                acc[r][1] = fma2(hb, w1.y, acc[r][1]);
                hb = pk2(hv.z, hv.z);
                acc[r][0] = fma2(hb, w2.x, acc[r][0]);
                acc[r][1] = fma2(hb, w2.y, acc[r][1]);
                hb = pk2(hv.w, hv.w);
                acc[r][0] = fma2(hb, w3v.x, acc[r][0]);
                acc[r][1] = fma2(hb, w3v.y, acc[r][1]);
            }
        }

        // epilogue: +b2, leaky, stash to o2
#pragma unroll
        for (int r = 0; r < 4; r++) {
            int er = 4 * te + r;
#pragma unroll
            for (int p = 0; p < 2; p++) {
                float a, b;
                up2(acc[r][p], a, b);
                int m0 = 4 * tm + 2 * p;
                o2[er * O2_STRIDE + m0 + 0] = lrelu(a + b2s[m0 + 0]);
                o2[er * O2_STRIDE + m0 + 1] = lrelu(b + b2s[m0 + 1]);
            }
        }
    }
    __syncthreads();

    // ---- phase 3: layers 3 (32->16, leaky) and 4 (16->1), thread-per-edge ----
    if (tid < EPB) {
        int eg = blockIdx.x * EPB + tid;
        unsigned long long a3[8];
#pragma unroll
        for (int p = 0; p < 8; p++) a3[p] = pk2(b3s[2 * p], b3s[2 * p + 1]);

        const float* row = o2 + tid * O2_STRIDE;
#pragma unroll 4
        for (int k2 = 0; k2 < 32; k2++) {
            unsigned long long xb;
            {
                float xv = row[k2];
                xb = pk2(xv, xv);
            }
            const ulonglong2 wA = *(const ulonglong2*)&w3s[k2 * 16 + 0];
            const ulonglong2 wB = *(const ulonglong2*)&w3s[k2 * 16 + 4];
            const ulonglong2 wC = *(const ulonglong2*)&w3s[k2 * 16 + 8];
            const ulonglong2 wD = *(const ulonglong2*)&w3s[k2 * 16 + 12];
            a3[0] = fma2(xb, wA.x, a3[0]);
            a3[1] = fma2(xb, wA.y, a3[1]);
            a3[2] = fma2(xb, wB.x, a3[2]);
            a3[3] = fma2(xb, wB.y, a3[3]);
            a3[4] = fma2(xb, wC.x, a3[4]);
            a3[5] = fma2(xb, wC.y, a3[5]);
            a3[6] = fma2(xb, wD.x, a3[6]);
            a3[7] = fma2(xb, wD.y, a3[7]);
        }

        float y = __ldg(&b4[0]);
#pragma unroll
        for (int p = 0; p < 8; p++) {
            float a, b;
            up2(a3[p], a, b);
            y = fmaf(lrelu(a), w4s[2 * p + 0], y);
            y = fmaf(lrelu(b), w4s[2 * p + 1], y);
        }
        if (eg < E) out[eg] = y;
    }
}

// ---------------------------------------------------------------------------
extern "C" void kernel_launch(void* const* d_in, const int* in_sizes, int n_in,
                              void* d_out, int out_size) {
    const float* xd  = (const float*)d_in[0];
    const float* xs  = (const float*)d_in[1];
    const void*  ell = d_in[2];
    const float* W1  = (const float*)d_in[3];
    const float* b1  = (const float*)d_in[4];
    const float* W2  = (const float*)d_in[5];
    const float* b2  = (const float*)d_in[6];
    const float* W3  = (const float*)d_in[7];
    const float* b3  = (const float*)d_in[8];
    const float* W4  = (const float*)d_in[9];
    const float* b4  = (const float*)d_in[10];
    float* out = (float*)d_out;

    int n_drug = in_sizes[0] / 100;
    int n_dis  = in_sizes[1] / 100;
    int E      = in_sizes[2] / 2;

    detect_idx_dtype<<<1, 1>>>((const long long*)ell);
    node_precompute<<<n_drug + n_dis, 128>>>(xd, xs, W1, b1, n_drug, n_dis);

    cudaFuncSetAttribute(edge_mlp_kernel,
                         cudaFuncAttributeMaxDynamicSharedMemorySize, SMEM_BYTES);
    int grid = (E + EPB - 1) / EPB;
    edge_mlp_kernel<<<grid, NTHR, SMEM_BYTES>>>(ell, W2, b2, W3, b3, W4, b4,
                                                out, E);
}